// round 1
// baseline (speedup 1.0000x reference)
#include <cuda_runtime.h>
#include <cuda_bf16.h>
#include <math.h>

// ---------------------------------------------------------------------------
// Problem constants
// ---------------------------------------------------------------------------
#define NB   256      // batch
#define TT   64       // time steps
#define INW  150      // input width
#define HH   1024     // hidden
#define G3   (3*HH)   // 3072 gates
#define H2   (2*HH)   // 2048 concat width
#define NT   (NB*TT)  // 16384 rows
#define NCLS 60

// ---------------------------------------------------------------------------
// Device scratch (static — no allocations allowed)
// ---------------------------------------------------------------------------
__device__ float g_xn  [(size_t)NT * INW];          // normalized input
__device__ float g_gi  [2][(size_t)NT * G3];        // input-gate preactivations per dir
__device__ float g_bufA[(size_t)NT * H2];           // layer output ping
__device__ float g_bufB[(size_t)NT * H2];           // layer output pong
__device__ float g_h   [2][(size_t)NB * HH];        // current hidden per dir
__device__ float g_gh  [2][(size_t)NB * G3];        // recurrent preactivations per dir
__device__ float g_bn  [2 * INW];                   // mean, inv_std

// ---------------------------------------------------------------------------
// BatchNorm statistics: one block per channel
// ---------------------------------------------------------------------------
__global__ void bn_stats_kernel(const float* __restrict__ x)
{
    int c = blockIdx.x;
    float s = 0.f, s2 = 0.f;
    for (int i = threadIdx.x; i < NT; i += blockDim.x) {
        float v = x[(size_t)i * INW + c];
        s += v; s2 += v * v;
    }
    __shared__ float sh0[256], sh1[256];
    sh0[threadIdx.x] = s; sh1[threadIdx.x] = s2;
    __syncthreads();
    for (int off = 128; off > 0; off >>= 1) {
        if (threadIdx.x < off) {
            sh0[threadIdx.x] += sh0[threadIdx.x + off];
            sh1[threadIdx.x] += sh1[threadIdx.x + off];
        }
        __syncthreads();
    }
    if (threadIdx.x == 0) {
        float mean = sh0[0] / (float)NT;
        float var  = sh1[0] / (float)NT - mean * mean;
        g_bn[c]        = mean;
        g_bn[INW + c]  = rsqrtf(var + 1e-5f);
    }
}

__global__ void bn_apply_kernel(const float* __restrict__ x,
                                const float* __restrict__ gamma,
                                const float* __restrict__ beta)
{
    size_t i = (size_t)blockIdx.x * blockDim.x + threadIdx.x;
    if (i >= (size_t)NT * INW) return;
    int c = (int)(i % INW);
    g_xn[i] = (x[i] - g_bn[c]) * g_bn[INW + c] * gamma[c] + beta[c];
}

// ---------------------------------------------------------------------------
// Generic fp32 GEMM:  C[M,N] = A[M,K] * B[N,K]^T + bias[N]
// blockIdx.z selects a "direction": each operand may have a z-stride.
// Tile 128x128x16, 256 threads, 8x8 per thread.
// ---------------------------------------------------------------------------
#define BM 128
#define BN 128
#define BK 16

__global__ __launch_bounds__(256, 2)
void gemm_tn_bias(const float* __restrict__ A, const float* __restrict__ B,
                  const float* __restrict__ bias, float* __restrict__ C,
                  int M, int N, int K,
                  long strideAz, long strideBz, long strideBiasz, long strideCz)
{
    __shared__ float As[BK][BM];
    __shared__ float Bs[BK][BN];

    int bz = blockIdx.z;
    A    += (long)bz * strideAz;
    B    += (long)bz * strideBz;
    bias += (long)bz * strideBiasz;
    C    += (long)bz * strideCz;

    int m0 = blockIdx.y * BM;
    int n0 = blockIdx.x * BN;
    int tid = threadIdx.x;
    int tx = tid & 15;     // 0..15  (cols)
    int ty = tid >> 4;     // 0..15  (rows)

    float acc[8][8];
    #pragma unroll
    for (int i = 0; i < 8; i++)
        #pragma unroll
        for (int j = 0; j < 8; j++) acc[i][j] = 0.f;

    int arow = tid >> 2;         // 0..63
    int acol = (tid & 3) * 4;    // 0,4,8,12

    for (int k0 = 0; k0 < K; k0 += BK) {
        #pragma unroll
        for (int half = 0; half < 2; half++) {
            int r  = arow + half * 64;
            int gm = m0 + r;
            int gn = n0 + r;
            #pragma unroll
            for (int j = 0; j < 4; j++) {
                int gk = k0 + acol + j;
                float va = 0.f, vb = 0.f;
                if (gm < M && gk < K) va = A[(long)gm * K + gk];
                if (gn < N && gk < K) vb = B[(long)gn * K + gk];
                As[acol + j][r] = va;
                Bs[acol + j][r] = vb;
            }
        }
        __syncthreads();

        #pragma unroll
        for (int kk = 0; kk < BK; kk++) {
            float a[8], b[8];
            #pragma unroll
            for (int i = 0; i < 8; i++) a[i] = As[kk][ty * 8 + i];
            #pragma unroll
            for (int i = 0; i < 8; i++) b[i] = Bs[kk][tx * 8 + i];
            #pragma unroll
            for (int i = 0; i < 8; i++)
                #pragma unroll
                for (int j = 0; j < 8; j++)
                    acc[i][j] += a[i] * b[j];
        }
        __syncthreads();
    }

    #pragma unroll
    for (int i = 0; i < 8; i++) {
        int gm = m0 + ty * 8 + i;
        if (gm >= M) continue;
        #pragma unroll
        for (int j = 0; j < 8; j++) {
            int gn = n0 + tx * 8 + j;
            if (gn < N) C[(long)gm * N + gn] = acc[i][j] + bias[gn];
        }
    }
}

// ---------------------------------------------------------------------------
// Zero hidden state
// ---------------------------------------------------------------------------
__global__ void hzero_kernel()
{
    size_t i = (size_t)blockIdx.x * blockDim.x + threadIdx.x;
    if (i < (size_t)2 * NB * HH) ((float*)g_h)[i] = 0.f;
}

// ---------------------------------------------------------------------------
// GRU gate elementwise:  (per step t, both "directions" — both forward in time,
// exactly as the reference, which never flips time for d=1)
// ---------------------------------------------------------------------------
__global__ void gru_gate_kernel(float* __restrict__ outbuf, int t)
{
    int idx = blockIdx.x * blockDim.x + threadIdx.x;   // 2*256*1024
    if (idx >= 2 * NB * HH) return;
    int d   = idx >> 18;              // NB*HH = 2^18
    int rem = idx & ((1 << 18) - 1);
    int n   = rem >> 10;
    int j   = rem & (HH - 1);

    const float* gid = g_gi[d] + ((size_t)(n * TT + t)) * G3;
    const float* ghd = g_gh[d] + (size_t)n * G3;

    float i_r = gid[j], i_z = gid[HH + j], i_n = gid[2 * HH + j];
    float h_r = ghd[j], h_z = ghd[HH + j], h_n = ghd[2 * HH + j];

    float r  = 1.f / (1.f + expf(-(i_r + h_r)));
    float z  = 1.f / (1.f + expf(-(i_z + h_z)));
    float nn = tanhf(i_n + r * h_n);

    float* hp = &g_h[d][(size_t)n * HH + j];
    float h_old = *hp;
    float h_new = (1.f - z) * nn + z * h_old;
    *hp = h_new;

    outbuf[((size_t)(n * TT + t)) * H2 + d * HH + j] = h_new;
}

// ---------------------------------------------------------------------------
// FC head: out[n,c] = enc[n, T-1, :] . fc_w[c,:] + fc_b[c]
// ---------------------------------------------------------------------------
__global__ void fc_kernel(const float* __restrict__ enc,
                          const float* __restrict__ fc_w,
                          const float* __restrict__ fc_b,
                          float* __restrict__ out)
{
    int n = blockIdx.x;
    int c = threadIdx.x;
    if (c >= NCLS) return;
    const float* h = enc + ((size_t)n * TT + (TT - 1)) * H2;
    const float* w = fc_w + (size_t)c * H2;
    float s = 0.f;
    #pragma unroll 8
    for (int k = 0; k < H2; k++) s += h[k] * w[k];
    out[n * NCLS + c] = s + fc_b[c];
}

// ---------------------------------------------------------------------------
// Orchestration
// ---------------------------------------------------------------------------
extern "C" void kernel_launch(void* const* d_in, const int* in_sizes, int n_in,
                              void* d_out, int out_size)
{
    const float* x        = (const float*)d_in[0];
    const float* bn_gamma = (const float*)d_in[1];
    const float* bn_beta  = (const float*)d_in[2];
    const float* w_ih[3]  = {(const float*)d_in[3],  (const float*)d_in[7],  (const float*)d_in[11]};
    const float* w_hh[3]  = {(const float*)d_in[4],  (const float*)d_in[8],  (const float*)d_in[12]};
    const float* b_ih[3]  = {(const float*)d_in[5],  (const float*)d_in[9],  (const float*)d_in[13]};
    const float* b_hh[3]  = {(const float*)d_in[6],  (const float*)d_in[10], (const float*)d_in[14]};
    const float* fc_w     = (const float*)d_in[15];
    const float* fc_b     = (const float*)d_in[16];

    float* out = (float*)d_out;
    float* enc = out + (size_t)NB * NCLS;   // encoder_hidden region

    float *p_xn, *p_gi, *p_bufA, *p_bufB, *p_h, *p_gh;
    cudaGetSymbolAddress((void**)&p_xn,   g_xn);
    cudaGetSymbolAddress((void**)&p_gi,   g_gi);
    cudaGetSymbolAddress((void**)&p_bufA, g_bufA);
    cudaGetSymbolAddress((void**)&p_bufB, g_bufB);
    cudaGetSymbolAddress((void**)&p_h,    g_h);
    cudaGetSymbolAddress((void**)&p_gh,   g_gh);

    // ---- BatchNorm ----
    bn_stats_kernel<<<INW, 256>>>(x);
    {
        size_t n = (size_t)NT * INW;
        bn_apply_kernel<<<(unsigned)((n + 255) / 256), 256>>>(x, bn_gamma, bn_beta);
    }

    const float* layer_in[3] = {p_xn, p_bufA, p_bufB};
    float*       layer_out[3] = {p_bufA, p_bufB, enc};
    const int    layer_k[3]   = {INW, H2, H2};

    for (int l = 0; l < 3; l++) {
        int K = layer_k[l];

        // gi[d] = X @ w_ih[l][d]^T + b_ih[l][d]   for both dirs (grid.z)
        {
            dim3 grid(G3 / BN, NT / BM, 2);
            gemm_tn_bias<<<grid, 256>>>(layer_in[l], w_ih[l], b_ih[l], p_gi,
                                        NT, G3, K,
                                        0L,
                                        (long)G3 * K,
                                        (long)G3,
                                        (long)NT * G3);
        }

        // zero hidden state
        hzero_kernel<<<(2 * NB * HH) / 256, 256>>>();

        // sequential time steps
        for (int t = 0; t < TT; t++) {
            // gh[d] = h[d] @ w_hh[l][d]^T + b_hh[l][d]
            dim3 grid(G3 / BN, NB / BM, 2);
            gemm_tn_bias<<<grid, 256>>>(p_h, w_hh[l], b_hh[l], p_gh,
                                        NB, G3, HH,
                                        (long)NB * HH,
                                        (long)G3 * HH,
                                        (long)G3,
                                        (long)NB * G3);

            gru_gate_kernel<<<(2 * NB * HH) / 256, 256>>>(layer_out[l], t);
        }
    }

    // ---- FC head ----
    fc_kernel<<<NB, 64>>>(enc, fc_w, fc_b, out);
}

// round 3
// speedup vs baseline: 2.4110x; 2.4110x over previous
#include <cuda_runtime.h>
#include <cstdint>
#include <math.h>

// ---------------------------------------------------------------------------
// Problem constants
// ---------------------------------------------------------------------------
#define NB   256
#define TT   64
#define INW  150
#define INWP 160          // padded to multiple of 16 for K-tiling
#define HH   1024
#define G3   (3*HH)
#define H2   (2*HH)
#define NT   (NB*TT)
#define NCLS 60

// ---------------------------------------------------------------------------
// Device scratch
// ---------------------------------------------------------------------------
__device__ float g_xn  [(size_t)NT * INWP];
__device__ float g_wih0[(size_t)2 * G3 * INWP];
__device__ float g_gi  [2][(size_t)NT * G3];
__device__ float g_bufA[(size_t)NT * H2];
__device__ float g_bufB[(size_t)NT * H2];
__device__ float g_h   [2][(size_t)NB * HH];
__device__ float g_gh  [2][(size_t)NB * G3];
__device__ float g_bn  [2 * INW];

// ---------------------------------------------------------------------------
// mma.sync tf32 helpers (plain compute_103 PTX — no tcgen05 available)
// ---------------------------------------------------------------------------
__device__ __forceinline__ uint32_t f2tf32(float x) {
    uint32_t r;
    asm("cvt.rna.tf32.f32 %0, %1;" : "=r"(r) : "f"(x));
    return r;
}

__device__ __forceinline__ void mma_tf32(float* d,
                                         uint32_t a0, uint32_t a1, uint32_t a2, uint32_t a3,
                                         uint32_t b0, uint32_t b1)
{
    asm volatile(
        "mma.sync.aligned.m16n8k8.row.col.f32.tf32.tf32.f32 "
        "{%0,%1,%2,%3}, {%4,%5,%6,%7}, {%8,%9}, {%0,%1,%2,%3};"
        : "+f"(d[0]), "+f"(d[1]), "+f"(d[2]), "+f"(d[3])
        : "r"(a0), "r"(a1), "r"(a2), "r"(a3), "r"(b0), "r"(b1));
}

// ---------------------------------------------------------------------------
// BatchNorm
// ---------------------------------------------------------------------------
__global__ void bn_stats_kernel(const float* __restrict__ x)
{
    int c = blockIdx.x;
    float s = 0.f, s2 = 0.f;
    for (int i = threadIdx.x; i < NT; i += blockDim.x) {
        float v = x[(size_t)i * INW + c];
        s += v; s2 += v * v;
    }
    __shared__ float sh0[256], sh1[256];
    sh0[threadIdx.x] = s; sh1[threadIdx.x] = s2;
    __syncthreads();
    for (int off = 128; off > 0; off >>= 1) {
        if (threadIdx.x < off) {
            sh0[threadIdx.x] += sh0[threadIdx.x + off];
            sh1[threadIdx.x] += sh1[threadIdx.x + off];
        }
        __syncthreads();
    }
    if (threadIdx.x == 0) {
        float mean = sh0[0] / (float)NT;
        float var  = sh1[0] / (float)NT - mean * mean;
        g_bn[c]       = mean;
        g_bn[INW + c] = rsqrtf(var + 1e-5f);
    }
}

// writes padded [NT, INWP] activations (cols >= INW are zero)
__global__ void bn_apply_kernel(const float* __restrict__ x,
                                const float* __restrict__ gamma,
                                const float* __restrict__ beta)
{
    size_t i = (size_t)blockIdx.x * blockDim.x + threadIdx.x;
    if (i >= (size_t)NT * INWP) return;
    int c = (int)(i % INWP);
    size_t r = i / INWP;
    float v = 0.f;
    if (c < INW)
        v = (x[r * INW + c] - g_bn[c]) * g_bn[INW + c] * gamma[c] + beta[c];
    g_xn[i] = v;
}

// pad w_ih_0 [2,3072,150] -> [2,3072,160]
__global__ void repack_wih0_kernel(const float* __restrict__ w)
{
    size_t i = (size_t)blockIdx.x * blockDim.x + threadIdx.x;
    if (i >= (size_t)2 * G3 * INWP) return;
    int c = (int)(i % INWP);
    size_t r = i / INWP;
    g_wih0[i] = (c < INW) ? w[r * INW + c] : 0.f;
}

// ---------------------------------------------------------------------------
// TF32 tensor-core GEMM:  C[M,N] = A[M,K] * B[N,K]^T + bias[N]
// CTA tile 128x128x16, 8 warps (2M x 4N), warp tile 64x32 (4x4 m16n8k8 frags).
// K-permuted padded SMEM: within each 8-wide k block, k stored at col
// 2*(k%4) + k/4, so fragment pairs (c, c+4) are adjacent -> ld.shared.v2.
// Requires M % 128 == 0, N % 128 == 0, K % 16 == 0.
// blockIdx.z selects direction via per-operand z-strides.
// ---------------------------------------------------------------------------
__global__ __launch_bounds__(256)
void gemm_tf32_mma(const float* __restrict__ A, const float* __restrict__ B,
                   const float* __restrict__ bias, float* __restrict__ C,
                   int M, int N, int K,
                   long sAz, long sBz, long sbz, long sCz)
{
    __shared__ uint32_t As[128][18];
    __shared__ uint32_t Bs[128][18];

    const int bz = blockIdx.z;
    A    += (long)bz * sAz;
    B    += (long)bz * sBz;
    bias += (long)bz * sbz;
    C    += (long)bz * sCz;

    const int n0 = blockIdx.x * 128;
    const int m0 = blockIdx.y * 128;
    const int tid  = threadIdx.x;
    const int wid  = tid >> 5;
    const int lane = tid & 31;
    const int wm = wid & 1;        // 0..1  (M)
    const int wn = wid >> 1;       // 0..3  (N)
    const int g  = lane >> 2;      // groupID 0..7
    const int c  = lane & 3;       // threadID_in_group 0..3

    // global load assignment: 2 threads per row, 8 floats each (2 float4)
    const int lrow = tid >> 1;         // 0..127
    const int lblk = tid & 1;          // which 8-wide k block
    const float* Aptr = A + (long)(m0 + lrow) * K + lblk * 8;
    const float* Bptr = B + (long)(n0 + lrow) * K + lblk * 8;

    float acc[4][4][4];
    #pragma unroll
    for (int i = 0; i < 4; i++)
        #pragma unroll
        for (int j = 0; j < 4; j++)
            #pragma unroll
            for (int q = 0; q < 4; q++) acc[i][j][q] = 0.f;

    const int KT = K >> 4;

    float4 pa0 = *(const float4*)(Aptr);
    float4 pa1 = *(const float4*)(Aptr + 4);
    float4 pb0 = *(const float4*)(Bptr);
    float4 pb1 = *(const float4*)(Bptr + 4);

    for (int kt = 0; kt < KT; kt++) {
        // store prefetched tile into permuted smem (with tf32 rounding)
        {
            uint32_t* ar = &As[lrow][lblk * 8];
            ar[0] = f2tf32(pa0.x); ar[2] = f2tf32(pa0.y);
            ar[4] = f2tf32(pa0.z); ar[6] = f2tf32(pa0.w);
            ar[1] = f2tf32(pa1.x); ar[3] = f2tf32(pa1.y);
            ar[5] = f2tf32(pa1.z); ar[7] = f2tf32(pa1.w);
            uint32_t* br = &Bs[lrow][lblk * 8];
            br[0] = f2tf32(pb0.x); br[2] = f2tf32(pb0.y);
            br[4] = f2tf32(pb0.z); br[6] = f2tf32(pb0.w);
            br[1] = f2tf32(pb1.x); br[3] = f2tf32(pb1.y);
            br[5] = f2tf32(pb1.z); br[7] = f2tf32(pb1.w);
        }
        __syncthreads();

        // prefetch next tile
        if (kt + 1 < KT) {
            Aptr += 16; Bptr += 16;
            pa0 = *(const float4*)(Aptr);
            pa1 = *(const float4*)(Aptr + 4);
            pb0 = *(const float4*)(Bptr);
            pb1 = *(const float4*)(Bptr + 4);
        }

        // two k8 MMA steps
        #pragma unroll
        for (int s = 0; s < 2; s++) {
            uint2 af0[4], af1[4], bf[4];
            #pragma unroll
            for (int i = 0; i < 4; i++) {
                af0[i] = *(const uint2*)&As[wm * 64 + i * 16 + g    ][s * 8 + 2 * c];
                af1[i] = *(const uint2*)&As[wm * 64 + i * 16 + g + 8][s * 8 + 2 * c];
            }
            #pragma unroll
            for (int j = 0; j < 4; j++)
                bf[j] = *(const uint2*)&Bs[wn * 32 + j * 8 + g][s * 8 + 2 * c];

            #pragma unroll
            for (int i = 0; i < 4; i++)
                #pragma unroll
                for (int j = 0; j < 4; j++)
                    mma_tf32(acc[i][j],
                             af0[i].x, af1[i].x, af0[i].y, af1[i].y,
                             bf[j].x, bf[j].y);
        }
        __syncthreads();
    }

    // epilogue
    #pragma unroll
    for (int i = 0; i < 4; i++) {
        const int row = m0 + wm * 64 + i * 16 + g;
        #pragma unroll
        for (int j = 0; j < 4; j++) {
            const int col = n0 + wn * 32 + j * 8 + 2 * c;
            const float bx = __ldg(&bias[col]);
            const float by = __ldg(&bias[col + 1]);
            float2 v0 = make_float2(acc[i][j][0] + bx, acc[i][j][1] + by);
            float2 v1 = make_float2(acc[i][j][2] + bx, acc[i][j][3] + by);
            *(float2*)&C[(long)row * N + col]       = v0;
            *(float2*)&C[(long)(row + 8) * N + col] = v1;
        }
    }
}

// ---------------------------------------------------------------------------
// hidden state zero
// ---------------------------------------------------------------------------
__global__ void hzero_kernel()
{
    size_t i = (size_t)blockIdx.x * blockDim.x + threadIdx.x;
    if (i < (size_t)2 * NB * HH) ((float*)g_h)[i] = 0.f;
}

// ---------------------------------------------------------------------------
// GRU gate elementwise (float4-vectorized)
// ---------------------------------------------------------------------------
__global__ void gru_gate_kernel(float* __restrict__ outbuf, int t)
{
    int idx = blockIdx.x * blockDim.x + threadIdx.x;  // 2*NB*HH/4 = 131072
    if (idx >= 2 * NB * HH / 4) return;
    int d   = idx >> 16;                    // NB*HH/4 = 65536
    int rem = idx & 65535;
    int n   = rem >> 8;                     // HH/4 = 256
    int jq  = rem & 255;

    const float4* gi = (const float4*)(g_gi[d] + (size_t)(n * TT + t) * G3);
    const float4* gh = (const float4*)(g_gh[d] + (size_t)n * G3);

    float4 ir = gi[jq],       hr = gh[jq];
    float4 iz = gi[256 + jq], hz = gh[256 + jq];
    float4 in = gi[512 + jq], hn = gh[512 + jq];

    float4* hp = (float4*)(g_h[d] + (size_t)n * HH) + jq;
    float4 ho = *hp;
    float4 hv;

    {
        float r = 1.f / (1.f + __expf(-(ir.x + hr.x)));
        float z = 1.f / (1.f + __expf(-(iz.x + hz.x)));
        float nn = tanhf(in.x + r * hn.x);
        hv.x = (1.f - z) * nn + z * ho.x;
    }
    {
        float r = 1.f / (1.f + __expf(-(ir.y + hr.y)));
        float z = 1.f / (1.f + __expf(-(iz.y + hz.y)));
        float nn = tanhf(in.y + r * hn.y);
        hv.y = (1.f - z) * nn + z * ho.y;
    }
    {
        float r = 1.f / (1.f + __expf(-(ir.z + hr.z)));
        float z = 1.f / (1.f + __expf(-(iz.z + hz.z)));
        float nn = tanhf(in.z + r * hn.z);
        hv.z = (1.f - z) * nn + z * ho.z;
    }
    {
        float r = 1.f / (1.f + __expf(-(ir.w + hr.w)));
        float z = 1.f / (1.f + __expf(-(iz.w + hz.w)));
        float nn = tanhf(in.w + r * hn.w);
        hv.w = (1.f - z) * nn + z * ho.w;
    }

    *hp = hv;
    *((float4*)(outbuf + (size_t)(n * TT + t) * H2 + d * HH) + jq) = hv;
}

// ---------------------------------------------------------------------------
// FC head
// ---------------------------------------------------------------------------
__global__ void fc_kernel(const float* __restrict__ enc,
                          const float* __restrict__ fc_w,
                          const float* __restrict__ fc_b,
                          float* __restrict__ out)
{
    int n = blockIdx.x;
    int c = threadIdx.x;
    if (c >= NCLS) return;
    const float* h = enc + ((size_t)n * TT + (TT - 1)) * H2;
    const float* w = fc_w + (size_t)c * H2;
    float s = 0.f;
    #pragma unroll 8
    for (int k = 0; k < H2; k++) s += h[k] * w[k];
    out[n * NCLS + c] = s + fc_b[c];
}

// ---------------------------------------------------------------------------
// Orchestration
// ---------------------------------------------------------------------------
extern "C" void kernel_launch(void* const* d_in, const int* in_sizes, int n_in,
                              void* d_out, int out_size)
{
    const float* x        = (const float*)d_in[0];
    const float* bn_gamma = (const float*)d_in[1];
    const float* bn_beta  = (const float*)d_in[2];
    const float* w_ih[3]  = {(const float*)d_in[3],  (const float*)d_in[7],  (const float*)d_in[11]};
    const float* w_hh[3]  = {(const float*)d_in[4],  (const float*)d_in[8],  (const float*)d_in[12]};
    const float* b_ih[3]  = {(const float*)d_in[5],  (const float*)d_in[9],  (const float*)d_in[13]};
    const float* b_hh[3]  = {(const float*)d_in[6],  (const float*)d_in[10], (const float*)d_in[14]};
    const float* fc_w     = (const float*)d_in[15];
    const float* fc_b     = (const float*)d_in[16];

    float* out = (float*)d_out;
    float* enc = out + (size_t)NB * NCLS;

    float *p_xn, *p_wih0, *p_gi, *p_bufA, *p_bufB, *p_h, *p_gh;
    cudaGetSymbolAddress((void**)&p_xn,   g_xn);
    cudaGetSymbolAddress((void**)&p_wih0, g_wih0);
    cudaGetSymbolAddress((void**)&p_gi,   g_gi);
    cudaGetSymbolAddress((void**)&p_bufA, g_bufA);
    cudaGetSymbolAddress((void**)&p_bufB, g_bufB);
    cudaGetSymbolAddress((void**)&p_h,    g_h);
    cudaGetSymbolAddress((void**)&p_gh,   g_gh);

    // ---- BatchNorm (padded output) + weight repack ----
    bn_stats_kernel<<<INW, 256>>>(x);
    {
        size_t n = (size_t)NT * INWP;
        bn_apply_kernel<<<(unsigned)((n + 255) / 256), 256>>>(x, bn_gamma, bn_beta);
    }
    {
        size_t n = (size_t)2 * G3 * INWP;
        repack_wih0_kernel<<<(unsigned)((n + 255) / 256), 256>>>(w_ih[0]);
    }

    const float* layer_in[3]  = {p_xn, p_bufA, p_bufB};
    float*       layer_out[3] = {p_bufA, p_bufB, enc};
    const int    layer_k[3]   = {INWP, H2, H2};
    const float* layer_wih[3] = {p_wih0, w_ih[1], w_ih[2]};

    for (int l = 0; l < 3; l++) {
        const int K = layer_k[l];

        // gi[d] = X @ w_ih[l][d]^T + b_ih[l][d]
        {
            dim3 grid(G3 / 128, NT / 128, 2);
            gemm_tf32_mma<<<grid, 256>>>(layer_in[l], layer_wih[l], b_ih[l], p_gi,
                                         NT, G3, K,
                                         0L, (long)G3 * K, (long)G3, (long)NT * G3);
        }

        hzero_kernel<<<(2 * NB * HH) / 256, 256>>>();

        for (int t = 0; t < TT; t++) {
            // gh[d] = h[d] @ w_hh[l][d]^T + b_hh[l][d]
            dim3 grid(G3 / 128, NB / 128, 2);
            gemm_tf32_mma<<<grid, 256>>>(p_h, w_hh[l], b_hh[l], p_gh,
                                         NB, G3, HH,
                                         (long)NB * HH, (long)G3 * HH,
                                         (long)G3, (long)NB * G3);

            gru_gate_kernel<<<512, 256>>>(layer_out[l], t);
        }
    }

    fc_kernel<<<NB, 64>>>(enc, fc_w, fc_b, out);
}

// round 4
// speedup vs baseline: 4.8081x; 1.9943x over previous
#include <cuda_runtime.h>
#include <cuda_fp16.h>
#include <cstdint>
#include <math.h>

// ---------------------------------------------------------------------------
// Problem constants
// ---------------------------------------------------------------------------
#define NB   256
#define TT   64
#define INW  150
#define INWP 160          // padded to multiple of 32 for K-tiling
#define HH   1024
#define G3   (3*HH)
#define H2   (2*HH)
#define NT   (NB*TT)
#define NCLS 60

// ---------------------------------------------------------------------------
// Device scratch
// ---------------------------------------------------------------------------
__device__ __half g_xn   [(size_t)NT * INWP];          // normalized input (half)
__device__ __half g_wih0h[(size_t)2 * G3 * INWP];      // padded layer-0 w_ih (half)
__device__ __half g_wih1h[(size_t)2 * G3 * H2];        // layer-1 w_ih (half)
__device__ __half g_wih2h[(size_t)2 * G3 * H2];        // layer-2 w_ih (half)
__device__ __half g_whhh [3][(size_t)2 * G3 * HH];     // w_hh all layers (half)
__device__ float  g_gi   [2][(size_t)NT * G3];         // input preactivations
__device__ __half g_bufAh[(size_t)NT * H2];            // layer-0 output (half)
__device__ __half g_bufBh[(size_t)NT * H2];            // layer-1 output (half)
__device__ float  g_h    [2][(size_t)NB * HH];         // fp32 master hidden state
__device__ __half g_hh   [2][(size_t)NB * HH];         // half copy for GEMM A
__device__ float  g_gh   [2][(size_t)NB * G3];         // recurrent preactivations
__device__ float  g_bn   [2 * INW];

// ---------------------------------------------------------------------------
// mma.sync fp16 helper (m16n8k16, fp32 accumulate)
// ---------------------------------------------------------------------------
__device__ __forceinline__ void mma_f16(float* d,
                                        uint32_t a0, uint32_t a1, uint32_t a2, uint32_t a3,
                                        uint32_t b0, uint32_t b1)
{
    asm volatile(
        "mma.sync.aligned.m16n8k16.row.col.f32.f16.f16.f32 "
        "{%0,%1,%2,%3}, {%4,%5,%6,%7}, {%8,%9}, {%0,%1,%2,%3};"
        : "+f"(d[0]), "+f"(d[1]), "+f"(d[2]), "+f"(d[3])
        : "r"(a0), "r"(a1), "r"(a2), "r"(a3), "r"(b0), "r"(b1));
}

// ---------------------------------------------------------------------------
// Weight conversion (fp32 -> fp16), generic grid-stride
// ---------------------------------------------------------------------------
__global__ void cvt_half_kernel(const float* __restrict__ src, __half* __restrict__ dst, size_t n)
{
    for (size_t i = (size_t)blockIdx.x * blockDim.x + threadIdx.x; i < n;
         i += (size_t)gridDim.x * blockDim.x)
        dst[i] = __float2half_rn(src[i]);
}

// pad w_ih_0 [2,3072,150] -> [2,3072,160] half
__global__ void cvt_wih0_kernel(const float* __restrict__ w)
{
    size_t i = (size_t)blockIdx.x * blockDim.x + threadIdx.x;
    if (i >= (size_t)2 * G3 * INWP) return;
    int c = (int)(i % INWP);
    size_t r = i / INWP;
    g_wih0h[i] = __float2half_rn((c < INW) ? w[r * INW + c] : 0.f);
}

// ---------------------------------------------------------------------------
// BatchNorm
// ---------------------------------------------------------------------------
__global__ void bn_stats_kernel(const float* __restrict__ x)
{
    int c = blockIdx.x;
    float s = 0.f, s2 = 0.f;
    for (int i = threadIdx.x; i < NT; i += blockDim.x) {
        float v = x[(size_t)i * INW + c];
        s += v; s2 += v * v;
    }
    __shared__ float sh0[256], sh1[256];
    sh0[threadIdx.x] = s; sh1[threadIdx.x] = s2;
    __syncthreads();
    for (int off = 128; off > 0; off >>= 1) {
        if (threadIdx.x < off) {
            sh0[threadIdx.x] += sh0[threadIdx.x + off];
            sh1[threadIdx.x] += sh1[threadIdx.x + off];
        }
        __syncthreads();
    }
    if (threadIdx.x == 0) {
        float mean = sh0[0] / (float)NT;
        float var  = sh1[0] / (float)NT - mean * mean;
        g_bn[c]       = mean;
        g_bn[INW + c] = rsqrtf(var + 1e-5f);
    }
}

__global__ void bn_apply_kernel(const float* __restrict__ x,
                                const float* __restrict__ gamma,
                                const float* __restrict__ beta)
{
    size_t i = (size_t)blockIdx.x * blockDim.x + threadIdx.x;
    if (i >= (size_t)NT * INWP) return;
    int c = (int)(i % INWP);
    size_t r = i / INWP;
    float v = 0.f;
    if (c < INW)
        v = (x[r * INW + c] - g_bn[c]) * g_bn[INW + c] * gamma[c] + beta[c];
    g_xn[i] = __float2half_rn(v);
}

// ---------------------------------------------------------------------------
// FP16 tensor-core GEMM:  C[M,N] = A[M,K] * B[N,K]^T + bias[N]   (fp32 accum)
// CTA tile 128x128x32, 8 warps (2M x 4N), warp tile 64x32 (4x4 m16n8k16).
// Double-buffered SMEM; K-permuted layout: within each 8-half2 k16 block,
// half2 k2 stored at col 2*(k2%4) + k2/4 so fragment pairs {c, c+4} are
// adjacent -> single ld.shared.v2 per fragment half.
// Row stride 24 words (=8 mod 32) -> conflict-free 16-lane LDS.64 phases.
// Requires M,N multiples of 128 and K multiple of 32.
// ---------------------------------------------------------------------------
__global__ __launch_bounds__(256)
void gemm_f16_mma(const __half* __restrict__ A, const __half* __restrict__ B,
                  const float* __restrict__ bias, float* __restrict__ C,
                  int M, int N, int K,
                  long sAz, long sBz, long sbz, long sCz)
{
    __shared__ uint32_t As[2][128][24];
    __shared__ uint32_t Bs[2][128][24];

    const int bz = blockIdx.z;
    A    += (long)bz * sAz;
    B    += (long)bz * sBz;
    bias += (long)bz * sbz;
    C    += (long)bz * sCz;

    const int n0 = blockIdx.x * 128;
    const int m0 = blockIdx.y * 128;
    const int tid  = threadIdx.x;
    const int wid  = tid >> 5;
    const int lane = tid & 31;
    const int wm = wid & 1;        // 0..1  (M)
    const int wn = wid >> 1;       // 0..3  (N)
    const int g  = lane >> 2;      // groupID 0..7
    const int c  = lane & 3;       // threadID_in_group 0..3

    // global load: 2 threads per row, each owns one k16 block (16 halves = 2 uint4)
    const int lrow = tid >> 1;
    const int lblk = tid & 1;
    const __half* Aptr = A + (long)(m0 + lrow) * K + lblk * 16;
    const __half* Bptr = B + (long)(n0 + lrow) * K + lblk * 16;

    float acc[4][4][4];
    #pragma unroll
    for (int i = 0; i < 4; i++)
        #pragma unroll
        for (int j = 0; j < 4; j++)
            #pragma unroll
            for (int q = 0; q < 4; q++) acc[i][j][q] = 0.f;

    const int KT = K >> 5;

    uint4 pa0 = *(const uint4*)(Aptr);
    uint4 pa1 = *(const uint4*)(Aptr + 8);
    uint4 pb0 = *(const uint4*)(Bptr);
    uint4 pb1 = *(const uint4*)(Bptr + 8);

    // store tile 0 into buffer 0 (permuted: dst[2j]=lo.j, dst[2j+1]=hi.j)
    {
        uint2* ar = (uint2*)&As[0][lrow][lblk * 8];
        ar[0] = make_uint2(pa0.x, pa1.x);
        ar[1] = make_uint2(pa0.y, pa1.y);
        ar[2] = make_uint2(pa0.z, pa1.z);
        ar[3] = make_uint2(pa0.w, pa1.w);
        uint2* br = (uint2*)&Bs[0][lrow][lblk * 8];
        br[0] = make_uint2(pb0.x, pb1.x);
        br[1] = make_uint2(pb0.y, pb1.y);
        br[2] = make_uint2(pb0.z, pb1.z);
        br[3] = make_uint2(pb0.w, pb1.w);
    }
    __syncthreads();

    for (int kt = 0; kt < KT; kt++) {
        const int buf = kt & 1;

        // prefetch + store next tile into the other buffer
        if (kt + 1 < KT) {
            Aptr += 32; Bptr += 32;
            pa0 = *(const uint4*)(Aptr);
            pa1 = *(const uint4*)(Aptr + 8);
            pb0 = *(const uint4*)(Bptr);
            pb1 = *(const uint4*)(Bptr + 8);
            uint2* ar = (uint2*)&As[buf ^ 1][lrow][lblk * 8];
            ar[0] = make_uint2(pa0.x, pa1.x);
            ar[1] = make_uint2(pa0.y, pa1.y);
            ar[2] = make_uint2(pa0.z, pa1.z);
            ar[3] = make_uint2(pa0.w, pa1.w);
            uint2* br = (uint2*)&Bs[buf ^ 1][lrow][lblk * 8];
            br[0] = make_uint2(pb0.x, pb1.x);
            br[1] = make_uint2(pb0.y, pb1.y);
            br[2] = make_uint2(pb0.z, pb1.z);
            br[3] = make_uint2(pb0.w, pb1.w);
        }

        // two k16 MMA steps from current buffer
        #pragma unroll
        for (int s = 0; s < 2; s++) {
            uint2 af0[4], af1[4], bf[4];
            #pragma unroll
            for (int i = 0; i < 4; i++) {
                af0[i] = *(const uint2*)&As[buf][wm * 64 + i * 16 + g    ][s * 8 + 2 * c];
                af1[i] = *(const uint2*)&As[buf][wm * 64 + i * 16 + g + 8][s * 8 + 2 * c];
            }
            #pragma unroll
            for (int j = 0; j < 4; j++)
                bf[j] = *(const uint2*)&Bs[buf][wn * 32 + j * 8 + g][s * 8 + 2 * c];

            #pragma unroll
            for (int i = 0; i < 4; i++)
                #pragma unroll
                for (int j = 0; j < 4; j++)
                    mma_f16(acc[i][j],
                            af0[i].x, af1[i].x, af0[i].y, af1[i].y,
                            bf[j].x, bf[j].y);
        }
        __syncthreads();
    }

    // epilogue
    #pragma unroll
    for (int i = 0; i < 4; i++) {
        const int row = m0 + wm * 64 + i * 16 + g;
        #pragma unroll
        for (int j = 0; j < 4; j++) {
            const int col = n0 + wn * 32 + j * 8 + 2 * c;
            const float bx = __ldg(&bias[col]);
            const float by = __ldg(&bias[col + 1]);
            float2 v0 = make_float2(acc[i][j][0] + bx, acc[i][j][1] + by);
            float2 v1 = make_float2(acc[i][j][2] + bx, acc[i][j][3] + by);
            *(float2*)&C[(long)row * N + col]       = v0;
            *(float2*)&C[(long)(row + 8) * N + col] = v1;
        }
    }
}

// ---------------------------------------------------------------------------
// hidden state zero (fp32 master + half copy)
// ---------------------------------------------------------------------------
__global__ void hzero_kernel()
{
    size_t i = (size_t)blockIdx.x * blockDim.x + threadIdx.x;
    if (i < (size_t)2 * NB * HH) {
        ((float*)g_h)[i] = 0.f;
        ((__half*)g_hh)[i] = __float2half_rn(0.f);
    }
}

// ---------------------------------------------------------------------------
// GRU gate elementwise. Writes fp32 state, half state copy, and the layer
// output (half for layers 0/1, fp32 for the final encoder output).
// ---------------------------------------------------------------------------
__global__ void gru_gate_kernel(__half* __restrict__ out_h, float* __restrict__ out_f, int t)
{
    int idx = blockIdx.x * blockDim.x + threadIdx.x;  // 2*NB*HH/4
    if (idx >= 2 * NB * HH / 4) return;
    int d   = idx >> 16;
    int rem = idx & 65535;
    int n   = rem >> 8;
    int jq  = rem & 255;

    const float4* gi = (const float4*)(g_gi[d] + (size_t)(n * TT + t) * G3);
    const float4* gh = (const float4*)(g_gh[d] + (size_t)n * G3);

    float4 ir = gi[jq],       hr = gh[jq];
    float4 iz = gi[256 + jq], hz = gh[256 + jq];
    float4 in = gi[512 + jq], hn = gh[512 + jq];

    float4* hp = (float4*)(g_h[d] + (size_t)n * HH) + jq;
    float4 ho = *hp;
    float4 hv;

    {
        float r = 1.f / (1.f + __expf(-(ir.x + hr.x)));
        float z = 1.f / (1.f + __expf(-(iz.x + hz.x)));
        float nn = tanhf(in.x + r * hn.x);
        hv.x = (1.f - z) * nn + z * ho.x;
    }
    {
        float r = 1.f / (1.f + __expf(-(ir.y + hr.y)));
        float z = 1.f / (1.f + __expf(-(iz.y + hz.y)));
        float nn = tanhf(in.y + r * hn.y);
        hv.y = (1.f - z) * nn + z * ho.y;
    }
    {
        float r = 1.f / (1.f + __expf(-(ir.z + hr.z)));
        float z = 1.f / (1.f + __expf(-(iz.z + hz.z)));
        float nn = tanhf(in.z + r * hn.z);
        hv.z = (1.f - z) * nn + z * ho.z;
    }
    {
        float r = 1.f / (1.f + __expf(-(ir.w + hr.w)));
        float z = 1.f / (1.f + __expf(-(iz.w + hz.w)));
        float nn = tanhf(in.w + r * hn.w);
        hv.w = (1.f - z) * nn + z * ho.w;
    }

    *hp = hv;

    __half2 h01 = __floats2half2_rn(hv.x, hv.y);
    __half2 h23 = __floats2half2_rn(hv.z, hv.w);
    __half2* hhp = (__half2*)(g_hh[d] + (size_t)n * HH + 4 * jq);
    hhp[0] = h01; hhp[1] = h23;

    size_t ob = (size_t)(n * TT + t) * H2 + (size_t)d * HH + 4 * jq;
    if (out_f) {
        *(float4*)(out_f + ob) = hv;
    } else {
        __half2* op = (__half2*)(out_h + ob);
        op[0] = h01; op[1] = h23;
    }
}

// ---------------------------------------------------------------------------
// FC head
// ---------------------------------------------------------------------------
__global__ void fc_kernel(const float* __restrict__ enc,
                          const float* __restrict__ fc_w,
                          const float* __restrict__ fc_b,
                          float* __restrict__ out)
{
    int n = blockIdx.x;
    int c = threadIdx.x;
    if (c >= NCLS) return;
    const float* h = enc + ((size_t)n * TT + (TT - 1)) * H2;
    const float* w = fc_w + (size_t)c * H2;
    float s = 0.f;
    #pragma unroll 8
    for (int k = 0; k < H2; k++) s += h[k] * w[k];
    out[n * NCLS + c] = s + fc_b[c];
}

// ---------------------------------------------------------------------------
// Orchestration
// ---------------------------------------------------------------------------
extern "C" void kernel_launch(void* const* d_in, const int* in_sizes, int n_in,
                              void* d_out, int out_size)
{
    const float* x        = (const float*)d_in[0];
    const float* bn_gamma = (const float*)d_in[1];
    const float* bn_beta  = (const float*)d_in[2];
    const float* w_ih[3]  = {(const float*)d_in[3],  (const float*)d_in[7],  (const float*)d_in[11]};
    const float* w_hh[3]  = {(const float*)d_in[4],  (const float*)d_in[8],  (const float*)d_in[12]};
    const float* b_ih[3]  = {(const float*)d_in[5],  (const float*)d_in[9],  (const float*)d_in[13]};
    const float* b_hh[3]  = {(const float*)d_in[6],  (const float*)d_in[10], (const float*)d_in[14]};
    const float* fc_w     = (const float*)d_in[15];
    const float* fc_b     = (const float*)d_in[16];

    float* out = (float*)d_out;
    float* enc = out + (size_t)NB * NCLS;

    __half *p_xn, *p_wih0h, *p_wih1h, *p_wih2h, *p_whhh, *p_bufAh, *p_bufBh, *p_hh;
    float  *p_gi, *p_h, *p_gh;
    cudaGetSymbolAddress((void**)&p_xn,    g_xn);
    cudaGetSymbolAddress((void**)&p_wih0h, g_wih0h);
    cudaGetSymbolAddress((void**)&p_wih1h, g_wih1h);
    cudaGetSymbolAddress((void**)&p_wih2h, g_wih2h);
    cudaGetSymbolAddress((void**)&p_whhh,  g_whhh);
    cudaGetSymbolAddress((void**)&p_gi,    g_gi);
    cudaGetSymbolAddress((void**)&p_bufAh, g_bufAh);
    cudaGetSymbolAddress((void**)&p_bufBh, g_bufBh);
    cudaGetSymbolAddress((void**)&p_h,     g_h);
    cudaGetSymbolAddress((void**)&p_hh,    g_hh);
    cudaGetSymbolAddress((void**)&p_gh,    g_gh);

    // ---- weight conversions (half) ----
    {
        size_t n0 = (size_t)2 * G3 * INWP;
        cvt_wih0_kernel<<<(unsigned)((n0 + 255) / 256), 256>>>(w_ih[0]);
        size_t n1 = (size_t)2 * G3 * H2;
        cvt_half_kernel<<<2048, 256>>>(w_ih[1], p_wih1h, n1);
        cvt_half_kernel<<<2048, 256>>>(w_ih[2], p_wih2h, n1);
        size_t nh = (size_t)2 * G3 * HH;
        cvt_half_kernel<<<2048, 256>>>(w_hh[0], p_whhh + 0 * nh, nh);
        cvt_half_kernel<<<2048, 256>>>(w_hh[1], p_whhh + 1 * nh, nh);
        cvt_half_kernel<<<2048, 256>>>(w_hh[2], p_whhh + 2 * nh, nh);
    }

    // ---- BatchNorm ----
    bn_stats_kernel<<<INW, 256>>>(x);
    {
        size_t n = (size_t)NT * INWP;
        bn_apply_kernel<<<(unsigned)((n + 255) / 256), 256>>>(x, bn_gamma, bn_beta);
    }

    const __half* layer_in[3]  = {p_xn, p_bufAh, p_bufBh};
    __half*       layer_outh[3] = {p_bufAh, p_bufBh, nullptr};
    float*        layer_outf[3] = {nullptr, nullptr, enc};
    const int     layer_k[3]   = {INWP, H2, H2};
    const __half* layer_wih[3] = {p_wih0h, p_wih1h, p_wih2h};
    const size_t  nh = (size_t)2 * G3 * HH;

    for (int l = 0; l < 3; l++) {
        const int K = layer_k[l];

        // gi[d] = X @ w_ih[l][d]^T + b_ih[l][d]
        {
            dim3 grid(G3 / 128, NT / 128, 2);
            gemm_f16_mma<<<grid, 256>>>(layer_in[l], layer_wih[l], b_ih[l], p_gi,
                                        NT, G3, K,
                                        0L, (long)G3 * K, (long)G3, (long)NT * G3);
        }

        hzero_kernel<<<(2 * NB * HH) / 256, 256>>>();

        for (int t = 0; t < TT; t++) {
            // gh[d] = h[d] @ w_hh[l][d]^T + b_hh[l][d]
            dim3 grid(G3 / 128, NB / 128, 2);
            gemm_f16_mma<<<grid, 256>>>(p_hh, p_whhh + (size_t)l * nh, b_hh[l], p_gh,
                                        NB, G3, HH,
                                        (long)NB * HH, (long)G3 * HH,
                                        (long)G3, (long)NB * G3);

            gru_gate_kernel<<<512, 256>>>(layer_outh[l], layer_outf[l], t);
        }
    }

    fc_kernel<<<NB, 64>>>(enc, fc_w, fc_b, out);
}